// round 1
// baseline (speedup 1.0000x reference)
#include <cuda_runtime.h>
#include <cuda_bf16.h>
#include <cstddef>

// Problem constants
#define BB 1024
#define TT 64
#define DD 256
#define HH 512
#define G4H 2048   // 4*H
#define LN_EPS 1e-5f

// ---------------------------------------------------------------------------
// Scratch (no cudaMalloc allowed -> __device__ globals)
// ---------------------------------------------------------------------------
__device__ float g_gx[(size_t)BB * TT * G4H];   // 512 MB: precomputed x@W_ih^T + b_ih + b_hh
__device__ float g_h[2][BB * HH];               // double-buffered hidden state
__device__ float g_c[BB * HH];                  // cell state

__device__ __forceinline__ float sigm(float x) {
    return 1.0f / (1.0f + __expf(-x));
}

// ---------------------------------------------------------------------------
// Init: copy h0,c0 into state scratch
// ---------------------------------------------------------------------------
__global__ void init_states(const float* __restrict__ h0, const float* __restrict__ c0) {
    int i = blockIdx.x * blockDim.x + threadIdx.x;
    if (i < BB * HH) {
        g_h[0][i] = h0[i];
        g_c[i]    = c0[i];
    }
}

// ---------------------------------------------------------------------------
// Input GEMM: gx[m, n] = sum_k x[m,k] * W_ih[n,k] + b_ih[n] + b_hh[n]
//   M = B*T = 65536, N = 2048, K = 256. Both operands K-major (NT GEMM).
//   128x128 tile, BK=16, 256 threads, 8x8 microtile.
// ---------------------------------------------------------------------------
#define IA_BM 128
#define IA_BN 128
#define IA_BK 16

__global__ __launch_bounds__(256, 2)
void gemm_input(const float* __restrict__ x, const float* __restrict__ W_ih,
                const float* __restrict__ b_ih, const float* __restrict__ b_hh) {
    __shared__ float As[IA_BK][IA_BM];
    __shared__ float Bs[IA_BK][IA_BN];

    const int bx = blockIdx.x;          // N tile (0..15)
    const int by = blockIdx.y;          // M tile (0..511)
    const int tid = threadIdx.x;        // 0..255
    const int tx = tid & 15;            // col-thread
    const int ty = tid >> 4;            // row-thread

    const int m0 = by * IA_BM;
    const int n0 = bx * IA_BN;

    float acc[8][8];
    #pragma unroll
    for (int i = 0; i < 8; i++)
        #pragma unroll
        for (int j = 0; j < 8; j++) acc[i][j] = 0.0f;

    for (int kt = 0; kt < DD; kt += IA_BK) {
        // Load A tile: 128 rows x 16 cols = 512 float4; 2 per thread.
        #pragma unroll
        for (int l = 0; l < 2; l++) {
            int idx = tid + l * 256;       // 0..511
            int r  = idx >> 2;             // 0..127
            int k4 = idx & 3;              // 0..3
            float4 v = *(const float4*)(x + (size_t)(m0 + r) * DD + kt + k4 * 4);
            As[k4 * 4 + 0][r] = v.x;
            As[k4 * 4 + 1][r] = v.y;
            As[k4 * 4 + 2][r] = v.z;
            As[k4 * 4 + 3][r] = v.w;
        }
        // Load B tile: 128 rows (output cols) x 16 k = 512 float4; 2 per thread.
        #pragma unroll
        for (int l = 0; l < 2; l++) {
            int idx = tid + l * 256;
            int r  = idx >> 2;
            int k4 = idx & 3;
            float4 v = *(const float4*)(W_ih + (size_t)(n0 + r) * DD + kt + k4 * 4);
            Bs[k4 * 4 + 0][r] = v.x;
            Bs[k4 * 4 + 1][r] = v.y;
            Bs[k4 * 4 + 2][r] = v.z;
            Bs[k4 * 4 + 3][r] = v.w;
        }
        __syncthreads();

        #pragma unroll
        for (int k = 0; k < IA_BK; k++) {
            float a[8], b[8];
            float4 a0 = *(const float4*)&As[k][ty * 8];
            float4 a1 = *(const float4*)&As[k][ty * 8 + 4];
            a[0]=a0.x; a[1]=a0.y; a[2]=a0.z; a[3]=a0.w;
            a[4]=a1.x; a[5]=a1.y; a[6]=a1.z; a[7]=a1.w;
            float4 b0 = *(const float4*)&Bs[k][tx * 8];
            float4 b1 = *(const float4*)&Bs[k][tx * 8 + 4];
            b[0]=b0.x; b[1]=b0.y; b[2]=b0.z; b[3]=b0.w;
            b[4]=b1.x; b[5]=b1.y; b[6]=b1.z; b[7]=b1.w;
            #pragma unroll
            for (int i = 0; i < 8; i++)
                #pragma unroll
                for (int j = 0; j < 8; j++)
                    acc[i][j] = fmaf(a[i], b[j], acc[i][j]);
        }
        __syncthreads();
    }

    // Epilogue: add bias, store.
    #pragma unroll
    for (int i = 0; i < 8; i++) {
        int m = m0 + ty * 8 + i;
        float* dst = g_gx + (size_t)m * G4H + n0 + tx * 8;
        #pragma unroll
        for (int j = 0; j < 8; j++) {
            int col = n0 + tx * 8 + j;
            dst[j] = acc[i][j] + b_ih[col] + b_hh[col];
        }
    }
}

// ---------------------------------------------------------------------------
// Fused LSTM step:
//   g[m, gate*H + col] = gx[m, t, gate*H+col] + sum_k (h_in[m,k]*mask[m]) * W_hh[gate*H+col, k]
//   c = sig(f)*(c*mask) + sig(i)*tanh(g);  h = sig(o)*tanh(c)
// Block tile: 64 rows x 32 cols PER GATE (4 gates share the A tile).
// 128 threads = 8 row-threads x 16 col-threads; per thread 8 rows x 2 cols x 4 gates.
// Double-buffered h: read g_h[t&1], write g_h[(t+1)&1]  -> no cross-block race.
// ---------------------------------------------------------------------------
#define LS_SM 64
#define LS_SN 32
#define LS_SK 16

__global__ __launch_bounds__(128, 4)
void lstm_step(const float* __restrict__ W_hh, const int* __restrict__ dones,
               float* __restrict__ out, int t) {
    __shared__ float As[LS_SK][LS_SM];         // masked h tile
    __shared__ float Bs[4][LS_SK][LS_SN];      // W_hh tiles for the 4 gates
    __shared__ float maskS[LS_SM];

    const float* __restrict__ h_in = g_h[t & 1];
    float* __restrict__ h_out      = g_h[(t + 1) & 1];

    const int tid = threadIdx.x;     // 0..127
    const int tx = tid & 15;         // col-thread: 2 cols per gate
    const int ty = tid >> 4;         // row-thread: 8 rows
    const int n0 = blockIdx.x * LS_SN;  // col tile within a gate (H)
    const int m0 = blockIdx.y * LS_SM;  // row tile (batch)

    // done-mask for the 64 rows of this block
    if (tid < LS_SM) {
        int m = m0 + tid;
        float dprev = (t == 0) ? 0.0f : (float)dones[(size_t)m * TT + (t - 1)];
        maskS[tid] = 1.0f - dprev;
    }
    __syncthreads();

    float acc[4][8][2];
    #pragma unroll
    for (int g = 0; g < 4; g++)
        #pragma unroll
        for (int i = 0; i < 8; i++) {
            acc[g][i][0] = 0.0f; acc[g][i][1] = 0.0f;
        }

    for (int kt = 0; kt < HH; kt += LS_SK) {
        // A tile: 64 x 16 = 256 float4; 2 per thread; mask applied at load.
        #pragma unroll
        for (int l = 0; l < 2; l++) {
            int idx = tid + l * 128;      // 0..255
            int r  = idx >> 2;            // 0..63
            int k4 = idx & 3;
            float mk = maskS[r];
            float4 v = *(const float4*)(h_in + (size_t)(m0 + r) * HH + kt + k4 * 4);
            As[k4 * 4 + 0][r] = v.x * mk;
            As[k4 * 4 + 1][r] = v.y * mk;
            As[k4 * 4 + 2][r] = v.z * mk;
            As[k4 * 4 + 3][r] = v.w * mk;
        }
        // B tiles: 4 gates x 32 x 16 = 512 float4; 4 per thread.
        #pragma unroll
        for (int l = 0; l < 4; l++) {
            int idx  = tid + l * 128;     // 0..511
            int gate = idx >> 7;          // 0..3
            int rem  = idx & 127;
            int n    = rem >> 2;          // 0..31
            int k4   = rem & 3;
            float4 v = *(const float4*)(W_hh + (size_t)(gate * HH + n0 + n) * HH + kt + k4 * 4);
            Bs[gate][k4 * 4 + 0][n] = v.x;
            Bs[gate][k4 * 4 + 1][n] = v.y;
            Bs[gate][k4 * 4 + 2][n] = v.z;
            Bs[gate][k4 * 4 + 3][n] = v.w;
        }
        __syncthreads();

        #pragma unroll
        for (int k = 0; k < LS_SK; k++) {
            float a[8];
            float4 a0 = *(const float4*)&As[k][ty * 8];
            float4 a1 = *(const float4*)&As[k][ty * 8 + 4];
            a[0]=a0.x; a[1]=a0.y; a[2]=a0.z; a[3]=a0.w;
            a[4]=a1.x; a[5]=a1.y; a[6]=a1.z; a[7]=a1.w;
            #pragma unroll
            for (int g = 0; g < 4; g++) {
                float2 b = *(const float2*)&Bs[g][k][tx * 2];
                #pragma unroll
                for (int i = 0; i < 8; i++) {
                    acc[g][i][0] = fmaf(a[i], b.x, acc[g][i][0]);
                    acc[g][i][1] = fmaf(a[i], b.y, acc[g][i][1]);
                }
            }
        }
        __syncthreads();
    }

    // Epilogue: gate math, state update, write h into out (pre-LN).
    #pragma unroll
    for (int i = 0; i < 8; i++) {
        int lr = ty * 8 + i;
        int m  = m0 + lr;
        float mk = maskS[lr];
        size_t gxbase = ((size_t)m * TT + t) * G4H;
        #pragma unroll
        for (int j = 0; j < 2; j++) {
            int col = n0 + tx * 2 + j;
            float gi = acc[0][i][j] + g_gx[gxbase + col];
            float gf = acc[1][i][j] + g_gx[gxbase + HH + col];
            float gg = acc[2][i][j] + g_gx[gxbase + 2 * HH + col];
            float go = acc[3][i][j] + g_gx[gxbase + 3 * HH + col];
            float cprev = g_c[(size_t)m * HH + col] * mk;
            float cn = sigm(gf) * cprev + sigm(gi) * tanhf(gg);
            float hn = sigm(go) * tanhf(cn);
            g_c[(size_t)m * HH + col] = cn;
            h_out[(size_t)m * HH + col] = hn;
            out[((size_t)m * TT + t) * HH + col] = hn;
        }
    }
}

// ---------------------------------------------------------------------------
// LayerNorm in-place over last dim (H=512). One 128-thread block per row.
// ---------------------------------------------------------------------------
__global__ __launch_bounds__(128)
void ln_kernel(float* __restrict__ out, const float* __restrict__ gamma,
               const float* __restrict__ beta) {
    __shared__ float red[8];
    const int row = blockIdx.x;          // 0..B*T-1
    const int tid = threadIdx.x;         // 0..127
    float* p = out + (size_t)row * HH;

    float4 v = ((const float4*)p)[tid];
    float s  = v.x + v.y + v.z + v.w;
    float sq = v.x * v.x + v.y * v.y + v.z * v.z + v.w * v.w;

    #pragma unroll
    for (int o = 16; o > 0; o >>= 1) {
        s  += __shfl_xor_sync(0xFFFFFFFFu, s, o);
        sq += __shfl_xor_sync(0xFFFFFFFFu, sq, o);
    }
    int warp = tid >> 5, lane = tid & 31;
    if (lane == 0) { red[warp] = s; red[4 + warp] = sq; }
    __syncthreads();
    s  = red[0] + red[1] + red[2] + red[3];
    sq = red[4] + red[5] + red[6] + red[7];

    float mu  = s * (1.0f / HH);
    float var = sq * (1.0f / HH) - mu * mu;
    float r   = rsqrtf(var + LN_EPS);

    float4 gm = ((const float4*)gamma)[tid];
    float4 bt = ((const float4*)beta)[tid];
    float4 y;
    y.x = gm.x * (v.x - mu) * r + bt.x;
    y.y = gm.y * (v.y - mu) * r + bt.y;
    y.z = gm.z * (v.z - mu) * r + bt.z;
    y.w = gm.w * (v.w - mu) * r + bt.w;
    ((float4*)p)[tid] = y;
}

// ---------------------------------------------------------------------------
// Copy final states (h_n, c_n) to the output tail.
// After 64 steps, final h lives in g_h[(63+1)&1] = g_h[0].
// ---------------------------------------------------------------------------
__global__ void copy_states(float* __restrict__ out) {
    int i = blockIdx.x * blockDim.x + threadIdx.x;
    if (i < BB * HH) {
        const size_t base = (size_t)BB * TT * HH;
        out[base + i]           = g_h[0][i];
        out[base + BB * HH + i] = g_c[i];
    }
}

// ---------------------------------------------------------------------------
// Launch
// ---------------------------------------------------------------------------
extern "C" void kernel_launch(void* const* d_in, const int* in_sizes, int n_in,
                              void* d_out, int out_size) {
    const float* x     = (const float*)d_in[0];
    const float* h0    = (const float*)d_in[1];
    const float* c0    = (const float*)d_in[2];
    const float* W_ih  = (const float*)d_in[3];
    const float* W_hh  = (const float*)d_in[4];
    const float* b_ih  = (const float*)d_in[5];
    const float* b_hh  = (const float*)d_in[6];
    const float* gamma = (const float*)d_in[7];
    const float* beta  = (const float*)d_in[8];
    const int*   dones = (const int*)d_in[9];
    float* out = (float*)d_out;

    init_states<<<(BB * HH + 255) / 256, 256>>>(h0, c0);

    dim3 gA(G4H / IA_BN, (BB * TT) / IA_BM);   // 16 x 512
    gemm_input<<<gA, 256>>>(x, W_ih, b_ih, b_hh);

    dim3 gS(HH / LS_SN, BB / LS_SM);           // 16 x 16 = 256 blocks
    for (int t = 0; t < TT; ++t)
        lstm_step<<<gS, 128>>>(W_hh, dones, out, t);

    ln_kernel<<<BB * TT, 128>>>(out, gamma, beta);
    copy_states<<<(BB * HH + 255) / 256, 256>>>(out);
}

// round 4
// speedup vs baseline: 2.5989x; 2.5989x over previous
#include <cuda_runtime.h>
#include <cuda_bf16.h>
#include <cstdint>
#include <cstddef>

// Problem constants
#define BB 1024
#define TT 64
#define DD 256
#define HH 512
#define LN_EPS 1e-5f

// Fused step GEMM: C[128 m, 128 n] per CTA, n = 32 hcols x 4 gates.
// K = H + D = 768 in 24 tiles of 32. 256 threads = 8 warps (2 m x 4 n).
// Warp tile 64 x 32, where the warp's 32 n = 8 hcols x 4 gates.
#define NCH 24
#define BK 32
#define ASTRIDE 36                       // 32 + 4 pad (floats); 36*4=144B, 16B-aligned
#define TILE_FLOATS (128 * ASTRIDE)      // 4608
// dynamic smem layout (floats)
#define OFF_A(s) ((s) * TILE_FLOATS)
#define OFF_B(s) (2 * TILE_FLOATS + (s) * TILE_FLOATS)
#define OFF_BIAS (4 * TILE_FLOATS)
#define SMEM_BYTES ((4 * TILE_FLOATS + 128) * 4)   // 74240

// ---------------------------------------------------------------------------
// Scratch state
// ---------------------------------------------------------------------------
__device__ float g_h[2][BB * HH];
__device__ float g_c[BB * HH];

__device__ __forceinline__ float sigm(float x) { return 1.0f / (1.0f + __expf(-x)); }

__device__ __forceinline__ uint32_t smem_u32(const void* p) {
    uint32_t a;
    asm("{ .reg .u64 t; cvta.to.shared.u64 t, %1; cvt.u32.u64 %0, t; }" : "=r"(a) : "l"(p));
    return a;
}

__device__ __forceinline__ uint32_t f2tf32(float x) {
    uint32_t r;
    asm("cvt.rna.tf32.f32 %0, %1;" : "=r"(r) : "f"(x));
    return r;
}

__device__ __forceinline__ void mma_tf32(float* d, const uint32_t* a, const uint32_t* b) {
    asm volatile(
        "mma.sync.aligned.m16n8k8.row.col.f32.tf32.tf32.f32 "
        "{%0,%1,%2,%3}, {%4,%5,%6,%7}, {%8,%9}, {%0,%1,%2,%3};"
        : "+f"(d[0]), "+f"(d[1]), "+f"(d[2]), "+f"(d[3])
        : "r"(a[0]), "r"(a[1]), "r"(a[2]), "r"(a[3]), "r"(b[0]), "r"(b[1]));
}

__device__ __forceinline__ void cp_async16(uint32_t smem_addr, const void* gptr) {
    asm volatile("cp.async.cg.shared.global [%0], [%1], 16;"
                 :: "r"(smem_addr), "l"(gptr));
}
#define CP_COMMIT() asm volatile("cp.async.commit_group;" ::: "memory")
#define CP_WAIT(n)  asm volatile("cp.async.wait_group %0;" :: "n"(n) : "memory")

// ---------------------------------------------------------------------------
// Init states
// ---------------------------------------------------------------------------
__global__ void init_states(const float* __restrict__ h0, const float* __restrict__ c0) {
    int i = blockIdx.x * blockDim.x + threadIdx.x;
    if (i < BB * HH) { g_h[0][i] = h0[i]; g_c[i] = c0[i]; }
}

// ---------------------------------------------------------------------------
// Fused LSTM step (tf32 mma.sync):
//   g = [h | x_t] @ [W_hh | W_ih]^T + b ; gate math; masked state store.
// State buffers hold h,c pre-masked for the NEXT step, so the GEMM A-path is
// a pure copy (cp.async-able). out gets unmasked h; t=63 stores unmasked.
// Grid (H/32, B/128) = (16, 8) = 128 CTAs, 256 threads.
// ---------------------------------------------------------------------------
__global__ __launch_bounds__(256, 1)
void lstm_step_mma(const float* __restrict__ x,
                   const float* __restrict__ W_ih, const float* __restrict__ W_hh,
                   const float* __restrict__ b_ih, const float* __restrict__ b_hh,
                   const int* __restrict__ dones, float* __restrict__ out, int t) {
    extern __shared__ float sm[];
    const uint32_t sb = smem_u32(sm);
    const int tid  = threadIdx.x;
    const int wid  = tid >> 5;
    const int lane = tid & 31;
    const int wm   = wid >> 2;           // 0..1  (m half)
    const int wn   = wid & 3;            // 0..3  (hcol octet)
    const int c0   = blockIdx.x * 32;    // H-col tile base
    const int m0   = blockIdx.y * 128;   // batch tile base
    const int lq   = lane >> 2;          // 0..7
    const int lr   = lane & 3;           // 0..3

    const float* __restrict__ h_in = g_h[t & 1];
    float* __restrict__ h_out      = g_h[(t + 1) & 1];

    // bias staging: biasS[gate*32 + hcol_local]
    if (tid < 128) {
        int gate = tid >> 5, hl = tid & 31;
        int col = gate * HH + c0 + hl;
        sm[OFF_BIAS + tid] = b_ih[col] + b_hh[col];
    }

    // ---- cp.async tile loader ----
    // A: 128 rows x 32 k-floats = 1024 float4, 4/thread.
    // B: smem row bn -> gate=(bn>>3)&3, hcl=(bn>>5)*8+(bn&7), grow=gate*H+c0+hcl
    auto load_tile = [&](int c, int stage) {
        const int kb = c * BK;
        const uint32_t abase = sb + OFF_A(stage) * 4;
        const uint32_t bbase = sb + OFF_B(stage) * 4;
        #pragma unroll
        for (int l = 0; l < 4; l++) {
            int idx = l * 256 + tid;
            int r = idx >> 3, q = idx & 7;
            const float* src;
            if (kb < HH) src = h_in + (size_t)(m0 + r) * HH + kb + q * 4;
            else         src = x + ((size_t)(m0 + r) * TT + t) * DD + (kb - HH) + q * 4;
            cp_async16(abase + (r * ASTRIDE + q * 4) * 4, src);
        }
        #pragma unroll
        for (int l = 0; l < 4; l++) {
            int idx = l * 256 + tid;
            int bn = idx >> 3, q = idx & 7;
            int gate = (bn >> 3) & 3;
            int grow = gate * HH + c0 + (bn >> 5) * 8 + (bn & 7);
            const float* src;
            if (kb < HH) src = W_hh + (size_t)grow * HH + kb + q * 4;
            else         src = W_ih + (size_t)grow * DD + (kb - HH) + q * 4;
            cp_async16(bbase + (bn * ASTRIDE + q * 4) * 4, src);
        }
        CP_COMMIT();
    };

    float acc[4][4][4];
    #pragma unroll
    for (int mt = 0; mt < 4; mt++)
        #pragma unroll
        for (int nt = 0; nt < 4; nt++)
            #pragma unroll
            for (int i = 0; i < 4; i++) acc[mt][nt][i] = 0.0f;

    load_tile(0, 0);

    for (int c = 0; c < NCH; c++) {
        const int stage = c & 1;
        if (c + 1 < NCH) {
            load_tile(c + 1, stage ^ 1);
            CP_WAIT(1);
        } else {
            CP_WAIT(0);
        }
        __syncthreads();

        const float* As = sm + OFF_A(stage);
        const float* Bs = sm + OFF_B(stage);

        #pragma unroll
        for (int k8 = 0; k8 < 4; k8++) {
            const int kk = k8 * 8;
            uint32_t af[4][4];
            #pragma unroll
            for (int mt = 0; mt < 4; mt++) {
                int r0 = wm * 64 + mt * 16 + lq;
                af[mt][0] = f2tf32(As[r0 * ASTRIDE + kk + lr]);
                af[mt][1] = f2tf32(As[(r0 + 8) * ASTRIDE + kk + lr]);
                af[mt][2] = f2tf32(As[r0 * ASTRIDE + kk + lr + 4]);
                af[mt][3] = f2tf32(As[(r0 + 8) * ASTRIDE + kk + lr + 4]);
            }
            uint32_t bf[4][2];
            #pragma unroll
            for (int nt = 0; nt < 4; nt++) {
                int bn = wn * 32 + nt * 8 + lq;
                bf[nt][0] = f2tf32(Bs[bn * ASTRIDE + kk + lr]);
                bf[nt][1] = f2tf32(Bs[bn * ASTRIDE + kk + lr + 4]);
            }
            #pragma unroll
            for (int mt = 0; mt < 4; mt++)
                #pragma unroll
                for (int nt = 0; nt < 4; nt++)
                    mma_tf32(acc[mt][nt], af[mt], bf[nt]);
        }
        __syncthreads();
    }

    // ---- Epilogue: gates in-register per thread (nt == gate) ----
    #pragma unroll
    for (int mt = 0; mt < 4; mt++) {
        #pragma unroll
        for (int half = 0; half < 2; half++) {
            const int m = m0 + wm * 64 + mt * 16 + lq + half * 8;
            float maskn = 1.0f;
            if (t < TT - 1) maskn = 1.0f - (float)dones[(size_t)m * TT + t];
            #pragma unroll
            for (int ci = 0; ci < 2; ci++) {
                const int idx = half * 2 + ci;
                const int hl = wn * 8 + lr * 2 + ci;     // hcol local (0..31)
                const int colh = c0 + hl;
                float gi = acc[mt][0][idx] + sm[OFF_BIAS + 0 * 32 + hl];
                float gf = acc[mt][1][idx] + sm[OFF_BIAS + 1 * 32 + hl];
                float gg = acc[mt][2][idx] + sm[OFF_BIAS + 2 * 32 + hl];
                float go = acc[mt][3][idx] + sm[OFF_BIAS + 3 * 32 + hl];
                const size_t sidx = (size_t)m * HH + colh;
                float cp = g_c[sidx];                    // pre-masked by prev step
                float cn = sigm(gf) * cp + sigm(gi) * tanhf(gg);
                float hn = sigm(go) * tanhf(cn);
                g_c[sidx]   = cn * maskn;
                h_out[sidx] = hn * maskn;
                out[((size_t)m * TT + t) * HH + colh] = hn;
            }
        }
    }
}

// ---------------------------------------------------------------------------
// LayerNorm in-place over H=512. One 128-thread block per row.
// ---------------------------------------------------------------------------
__global__ __launch_bounds__(128)
void ln_kernel(float* __restrict__ out, const float* __restrict__ gamma,
               const float* __restrict__ beta) {
    __shared__ float red[8];
    const int row = blockIdx.x;
    const int tid = threadIdx.x;
    float* p = out + (size_t)row * HH;

    float4 v = ((const float4*)p)[tid];
    float s  = v.x + v.y + v.z + v.w;
    float sq = v.x * v.x + v.y * v.y + v.z * v.z + v.w * v.w;
    #pragma unroll
    for (int o = 16; o > 0; o >>= 1) {
        s  += __shfl_xor_sync(0xFFFFFFFFu, s, o);
        sq += __shfl_xor_sync(0xFFFFFFFFu, sq, o);
    }
    int warp = tid >> 5, lane = tid & 31;
    if (lane == 0) { red[warp] = s; red[4 + warp] = sq; }
    __syncthreads();
    s  = red[0] + red[1] + red[2] + red[3];
    sq = red[4] + red[5] + red[6] + red[7];

    float mu  = s * (1.0f / HH);
    float var = sq * (1.0f / HH) - mu * mu;
    float rr  = rsqrtf(var + LN_EPS);

    float4 gm = ((const float4*)gamma)[tid];
    float4 bt = ((const float4*)beta)[tid];
    float4 y;
    y.x = gm.x * (v.x - mu) * rr + bt.x;
    y.y = gm.y * (v.y - mu) * rr + bt.y;
    y.z = gm.z * (v.z - mu) * rr + bt.z;
    y.w = gm.w * (v.w - mu) * rr + bt.w;
    ((float4*)p)[tid] = y;
}

// ---------------------------------------------------------------------------
// Copy final states. After 64 steps final (unmasked) h is in g_h[0].
// ---------------------------------------------------------------------------
__global__ void copy_states(float* __restrict__ out) {
    int i = blockIdx.x * blockDim.x + threadIdx.x;
    if (i < BB * HH) {
        const size_t base = (size_t)BB * TT * HH;
        out[base + i]           = g_h[0][i];
        out[base + BB * HH + i] = g_c[i];
    }
}

// ---------------------------------------------------------------------------
// Launch
// ---------------------------------------------------------------------------
extern "C" void kernel_launch(void* const* d_in, const int* in_sizes, int n_in,
                              void* d_out, int out_size) {
    const float* x     = (const float*)d_in[0];
    const float* h0    = (const float*)d_in[1];
    const float* c0    = (const float*)d_in[2];
    const float* W_ih  = (const float*)d_in[3];
    const float* W_hh  = (const float*)d_in[4];
    const float* b_ih  = (const float*)d_in[5];
    const float* b_hh  = (const float*)d_in[6];
    const float* gamma = (const float*)d_in[7];
    const float* beta  = (const float*)d_in[8];
    const int*   dones = (const int*)d_in[9];
    float* out = (float*)d_out;

    static bool attr_set = false;
    if (!attr_set) {
        cudaFuncSetAttribute(lstm_step_mma, cudaFuncAttributeMaxDynamicSharedMemorySize,
                             SMEM_BYTES);
        attr_set = true;
    }

    init_states<<<(BB * HH + 255) / 256, 256>>>(h0, c0);

    dim3 gS(HH / 32, BB / 128);   // 16 x 8 = 128 CTAs
    for (int t = 0; t < TT; ++t)
        lstm_step_mma<<<gS, 256, SMEM_BYTES>>>(x, W_ih, W_hh, b_ih, b_hh, dones, out, t);

    ln_kernel<<<BB * TT, 128>>>(out, gamma, beta);
    copy_states<<<(BB * HH + 255) / 256, 256>>>(out);
}

// round 6
// speedup vs baseline: 2.7215x; 1.0472x over previous
#include <cuda_runtime.h>
#include <cuda_bf16.h>
#include <cstdint>
#include <cstddef>

// Problem constants
#define BB 1024
#define TT 64
#define DD 256
#define HH 512
#define LN_EPS 1e-5f

// Fused step GEMM: C[64 m, 128 n] per CTA, n = 32 hcols x 4 gates.
// K = 768 in 24 chunks of 32. 256 threads = 8 warps (2 m x 4 n), warp tile 32x32.
#define NCH 24
#define BK 32
#define ASTRIDE 36                        // 32 + 4 pad floats; 144B, 16B-aligned
#define ATILE_F (64 * ASTRIDE)            // 2304
#define BTILE_F (128 * ASTRIDE)           // 4608
#define OFF_A(s) ((s) * ATILE_F)
#define OFF_B(s) (2 * ATILE_F + (s) * BTILE_F)
#define OFF_BIAS (2 * ATILE_F + 2 * BTILE_F)
#define SMEM_BYTES ((OFF_BIAS + 128) * 4)   // 55808

// ---------------------------------------------------------------------------
// Scratch (device globals; no cudaMalloc allowed)
// ---------------------------------------------------------------------------
__device__ float g_h[2][BB * HH];              // tf32-rounded hidden state
__device__ float g_c[BB * HH];                 // full fp32 cell state
__device__ float g_x[(size_t)BB * TT * DD];    // tf32-rounded x
__device__ float g_wB[16 * NCH * 128 * BK];    // tf32-rounded W in smem tile order

__device__ __forceinline__ float sigm(float x) { return 1.0f / (1.0f + __expf(-x)); }

__device__ __forceinline__ uint32_t smem_u32(const void* p) {
    uint32_t a;
    asm("{ .reg .u64 t; cvta.to.shared.u64 t, %1; cvt.u32.u64 %0, t; }" : "=r"(a) : "l"(p));
    return a;
}

__device__ __forceinline__ uint32_t f2tf32(float x) {
    uint32_t r;
    asm("cvt.rna.tf32.f32 %0, %1;" : "=r"(r) : "f"(x));
    return r;
}

__device__ __forceinline__ void mma_tf32(float* d, const uint32_t* a, const uint32_t* b) {
    asm volatile(
        "mma.sync.aligned.m16n8k8.row.col.f32.tf32.tf32.f32 "
        "{%0,%1,%2,%3}, {%4,%5,%6,%7}, {%8,%9}, {%0,%1,%2,%3};"
        : "+f"(d[0]), "+f"(d[1]), "+f"(d[2]), "+f"(d[3])
        : "r"(a[0]), "r"(a[1]), "r"(a[2]), "r"(a[3]), "r"(b[0]), "r"(b[1]));
}

__device__ __forceinline__ void cp_async16(uint32_t smem_addr, const void* gptr) {
    asm volatile("cp.async.cg.shared.global [%0], [%1], 16;"
                 :: "r"(smem_addr), "l"(gptr));
}
#define CP_COMMIT() asm volatile("cp.async.commit_group;" ::: "memory")
#define CP_WAIT(n)  asm volatile("cp.async.wait_group %0;" :: "n"(n) : "memory")

// ---------------------------------------------------------------------------
// Prep kernels (rounding hoisted out of the hot loop)
// ---------------------------------------------------------------------------
// Weights into smem-tile order: g_wB[ct][chunk][bn][k], all rna-rounded.
// bn -> gate=(bn>>3)&3, hcl=(bn>>5)*8+(bn&7), grow = gate*H + ct*32 + hcl.
__global__ void prep_weights(const float* __restrict__ W_ih,
                             const float* __restrict__ W_hh) {
    const int ct = blockIdx.x;        // 0..15
    const int c  = blockIdx.y;        // 0..23
    const int kb = c * BK;
    float* dst = g_wB + ((size_t)(ct * NCH + c)) * (128 * BK);
    for (int i = threadIdx.x; i < 128 * BK; i += blockDim.x) {
        int bn = i >> 5, k = i & 31;
        int gate = (bn >> 3) & 3;
        int grow = gate * HH + ct * 32 + (bn >> 5) * 8 + (bn & 7);
        float v;
        if (kb < HH) v = W_hh[(size_t)grow * HH + kb + k];
        else         v = W_ih[(size_t)grow * DD + (kb - HH) + k];
        dst[i] = __uint_as_float(f2tf32(v));
    }
}

__global__ void prep_x(const float* __restrict__ x) {
    size_t i = (size_t)blockIdx.x * blockDim.x + threadIdx.x;
    if (i < (size_t)BB * TT * DD) g_x[i] = __uint_as_float(f2tf32(x[i]));
}

__global__ void init_states(const float* __restrict__ h0, const float* __restrict__ c0) {
    int i = blockIdx.x * blockDim.x + threadIdx.x;
    if (i < BB * HH) {
        g_h[0][i] = __uint_as_float(f2tf32(h0[i]));
        g_c[i]    = c0[i];
    }
}

// ---------------------------------------------------------------------------
// Fused LSTM step (tf32 mma.sync, no in-loop cvt):
//   g = [h | x_t] @ [W_hh | W_ih]^T + b ; gate math; masked state store.
// Grid (H/32, B/64) = (16, 16) = 256 CTAs, 256 threads, 2 CTAs/SM.
// ---------------------------------------------------------------------------
__global__ __launch_bounds__(256, 2)
void lstm_step_mma(const float* __restrict__ b_ih, const float* __restrict__ b_hh,
                   const int* __restrict__ dones, float* __restrict__ out, int t) {
    extern __shared__ float sm[];
    const uint32_t sb = smem_u32(sm);
    const int tid  = threadIdx.x;
    const int wid  = tid >> 5;
    const int lane = tid & 31;
    const int wm   = wid >> 2;           // 0..1  (m half, 32 rows each)
    const int wn   = wid & 3;            // 0..3  (hcol octet)
    const int ct   = blockIdx.x;         // H-col tile index
    const int c0   = ct * 32;
    const int m0   = blockIdx.y * 64;    // batch tile base
    const int lq   = lane >> 2;          // 0..7
    const int lr   = lane & 3;           // 0..3

    const float* __restrict__ h_in = g_h[t & 1];
    float* __restrict__ h_out      = g_h[(t + 1) & 1];

    // bias staging: biasS[gate*32 + hcol_local]
    if (tid < 128) {
        int gate = tid >> 5, hl = tid & 31;
        int col = gate * HH + c0 + hl;
        sm[OFF_BIAS + tid] = b_ih[col] + b_hh[col];
    }

    const float* __restrict__ wbase = g_wB + (size_t)ct * NCH * 128 * BK;

    // ---- cp.async tile loader ----
    auto load_tile = [&](int c, int stage) {
        const int kb = c * BK;
        const uint32_t abase = sb + OFF_A(stage) * 4;
        const uint32_t bbase = sb + OFF_B(stage) * 4;
        // A: 64 rows x 32 k = 512 float4, 2/thread
        #pragma unroll
        for (int l = 0; l < 2; l++) {
            int idx = l * 256 + tid;
            int r = idx >> 3, q = idx & 7;
            const float* src;
            if (kb < HH) src = h_in + (size_t)(m0 + r) * HH + kb + q * 4;
            else         src = g_x + ((size_t)(m0 + r) * TT + t) * DD + (kb - HH) + q * 4;
            cp_async16(abase + (r * ASTRIDE + q * 4) * 4, src);
        }
        // B: pre-arranged linear, 1024 float4, 4/thread
        const float* bsrc = wbase + (size_t)c * (128 * BK);
        #pragma unroll
        for (int l = 0; l < 4; l++) {
            int idx = l * 256 + tid;
            int bn = idx >> 3, q = idx & 7;
            cp_async16(bbase + (bn * ASTRIDE + q * 4) * 4, bsrc + idx * 4);
        }
        CP_COMMIT();
    };

    float acc[2][4][4];
    #pragma unroll
    for (int mt = 0; mt < 2; mt++)
        #pragma unroll
        for (int nt = 0; nt < 4; nt++)
            #pragma unroll
            for (int i = 0; i < 4; i++) acc[mt][nt][i] = 0.0f;

    load_tile(0, 0);

    for (int c = 0; c < NCH; c++) {
        const int stage = c & 1;
        if (c + 1 < NCH) {
            load_tile(c + 1, stage ^ 1);
            CP_WAIT(1);
        } else {
            CP_WAIT(0);
        }
        __syncthreads();

        const uint32_t* As = (const uint32_t*)(sm + OFF_A(stage));
        const uint32_t* Bs = (const uint32_t*)(sm + OFF_B(stage));

        #pragma unroll
        for (int k8 = 0; k8 < 4; k8++) {
            const int kk = k8 * 8;
            uint32_t af[2][4];
            #pragma unroll
            for (int mt = 0; mt < 2; mt++) {
                int r0 = wm * 32 + mt * 16 + lq;
                af[mt][0] = As[r0 * ASTRIDE + kk + lr];
                af[mt][1] = As[(r0 + 8) * ASTRIDE + kk + lr];
                af[mt][2] = As[r0 * ASTRIDE + kk + lr + 4];
                af[mt][3] = As[(r0 + 8) * ASTRIDE + kk + lr + 4];
            }
            uint32_t bf[4][2];
            #pragma unroll
            for (int nt = 0; nt < 4; nt++) {
                int bn = wn * 32 + nt * 8 + lq;
                bf[nt][0] = Bs[bn * ASTRIDE + kk + lr];
                bf[nt][1] = Bs[bn * ASTRIDE + kk + lr + 4];
            }
            #pragma unroll
            for (int mt = 0; mt < 2; mt++)
                #pragma unroll
                for (int nt = 0; nt < 4; nt++)
                    mma_tf32(acc[mt][nt], af[mt], bf[nt]);
        }
        __syncthreads();
    }

    // ---- Epilogue: gates in-register per thread (nt == gate) ----
    #pragma unroll
    for (int mt = 0; mt < 2; mt++) {
        #pragma unroll
        for (int half = 0; half < 2; half++) {
            const int m = m0 + wm * 32 + mt * 16 + lq + half * 8;
            float maskn = 1.0f;
            if (t < TT - 1) maskn = 1.0f - (float)dones[(size_t)m * TT + t];
            #pragma unroll
            for (int ci = 0; ci < 2; ci++) {
                const int idx = half * 2 + ci;
                const int hl = wn * 8 + lr * 2 + ci;     // hcol local (0..31)
                const int colh = c0 + hl;
                float gi = acc[mt][0][idx] + sm[OFF_BIAS + 0 * 32 + hl];
                float gf = acc[mt][1][idx] + sm[OFF_BIAS + 1 * 32 + hl];
                float gg = acc[mt][2][idx] + sm[OFF_BIAS + 2 * 32 + hl];
                float go = acc[mt][3][idx] + sm[OFF_BIAS + 3 * 32 + hl];
                const size_t sidx = (size_t)m * HH + colh;
                float cp = g_c[sidx];                    // pre-masked by prev step
                float cn = sigm(gf) * cp + sigm(gi) * tanhf(gg);
                float hn = sigm(go) * tanhf(cn);
                g_c[sidx]   = cn * maskn;
                h_out[sidx] = __uint_as_float(f2tf32(hn)) * maskn;  // MMA input: rounded
                out[((size_t)m * TT + t) * HH + colh] = hn;          // full precision
            }
        }
    }
}

// ---------------------------------------------------------------------------
// Copy final states BEFORE LayerNorm: h_n = out[:, T-1, :] (full precision,
// unmasked), c_n = g_c (unmasked at t=T-1).
// ---------------------------------------------------------------------------
__global__ void copy_states(float* __restrict__ out) {
    int i = blockIdx.x * blockDim.x + threadIdx.x;
    if (i < BB * HH) {
        const size_t base = (size_t)BB * TT * HH;
        int m = i / HH, col = i % HH;
        out[base + i]           = out[((size_t)m * TT + (TT - 1)) * HH + col];
        out[base + BB * HH + i] = g_c[i];
    }
}

// ---------------------------------------------------------------------------
// LayerNorm in-place over H=512. One 128-thread block per row.
// ---------------------------------------------------------------------------
__global__ __launch_bounds__(128)
void ln_kernel(float* __restrict__ out, const float* __restrict__ gamma,
               const float* __restrict__ beta) {
    __shared__ float red[8];
    const int row = blockIdx.x;
    const int tid = threadIdx.x;
    float* p = out + (size_t)row * HH;

    float4 v = ((const float4*)p)[tid];
    float s  = v.x + v.y + v.z + v.w;
    float sq = v.x * v.x + v.y * v.y + v.z * v.z + v.w * v.w;
    #pragma unroll
    for (int o = 16; o > 0; o >>= 1) {
        s  += __shfl_xor_sync(0xFFFFFFFFu, s, o);
        sq += __shfl_xor_sync(0xFFFFFFFFu, sq, o);
    }
    int warp = tid >> 5, lane = tid & 31;
    if (lane == 0) { red[warp] = s; red[4 + warp] = sq; }
    __syncthreads();
    s  = red[0] + red[1] + red[2] + red[3];
    sq = red[4] + red[5] + red[6] + red[7];

    float mu  = s * (1.0f / HH);
    float var = sq * (1.0f / HH) - mu * mu;
    float rr  = rsqrtf(var + LN_EPS);

    float4 gm = ((const float4*)gamma)[tid];
    float4 bt = ((const float4*)beta)[tid];
    float4 y;
    y.x = gm.x * (v.x - mu) * rr + bt.x;
    y.y = gm.y * (v.y - mu) * rr + bt.y;
    y.z = gm.z * (v.z - mu) * rr + bt.z;
    y.w = gm.w * (v.w - mu) * rr + bt.w;
    ((float4*)p)[tid] = y;
}

// ---------------------------------------------------------------------------
// Launch
// ---------------------------------------------------------------------------
extern "C" void kernel_launch(void* const* d_in, const int* in_sizes, int n_in,
                              void* d_out, int out_size) {
    const float* x     = (const float*)d_in[0];
    const float* h0    = (const float*)d_in[1];
    const float* c0    = (const float*)d_in[2];
    const float* W_ih  = (const float*)d_in[3];
    const float* W_hh  = (const float*)d_in[4];
    const float* b_ih  = (const float*)d_in[5];
    const float* b_hh  = (const float*)d_in[6];
    const float* gamma = (const float*)d_in[7];
    const float* beta  = (const float*)d_in[8];
    const int*   dones = (const int*)d_in[9];
    float* out = (float*)d_out;

    cudaFuncSetAttribute(lstm_step_mma, cudaFuncAttributeMaxDynamicSharedMemorySize,
                         SMEM_BYTES);

    init_states<<<(BB * HH + 255) / 256, 256>>>(h0, c0);
    prep_weights<<<dim3(16, NCH), 256>>>(W_ih, W_hh);
    prep_x<<<(int)(((size_t)BB * TT * DD + 255) / 256), 256>>>(x);

    dim3 gS(HH / 32, BB / 64);   // 16 x 16 = 256 CTAs
    for (int t = 0; t < TT; ++t)
        lstm_step_mma<<<gS, 256, SMEM_BYTES>>>(b_ih, b_hh, dones, out, t);

    copy_states<<<(BB * HH + 255) / 256, 256>>>(out);
    ln_kernel<<<BB * TT, 128>>>(out, gamma, beta);
}

// round 7
// speedup vs baseline: 3.7686x; 1.3847x over previous
#include <cuda_runtime.h>
#include <cuda_bf16.h>
#include <cstdint>
#include <cstddef>

// Problem constants
#define BB 1024
#define TT 64
#define DD 256
#define HH 512
#define LN_EPS 1e-5f

// Fused step GEMM: C[64 m, 128 n] per CTA, n = 32 hcols x 4 gates.
// K = 768 in 12 chunks of 64. 256 threads = 8 warps (wm 0..1 x wn 0..3).
// All operands stored in mma-fragment order as float4 quads:
//  A quad (thread lq,lr; rowblk, k8, mt): slots s=pair*2+half =
//     {A[r][k], A[r+8][k], A[r][k+4], A[r+8][k+4]}, r=rowblk*32+mt*16+half*8+lq, k=k8*8+lr
//  B quad (thread lq,lr; k8, wn, q): slots s=(nt&1)*2+pair, nt=q*2+(s>>1) =
//     W[bn][k], bn=wn*32+nt*8+lq, k=k8*8+lr+pair*4
#define NCH 12
#define BK 64
#define ATILE_F4 1024                 // 2 rowblk x 8 k8 x 2 mt x 32 lanes
#define BTILE_F4 2048                 // 8 k8 x 4 wn x 2 q x 32 lanes
#define OFF_A4(s) ((s) * ATILE_F4)
#define OFF_B4(s) (2 * ATILE_F4 + (s) * BTILE_F4)
#define OFF_BIAS4 (2 * ATILE_F4 + 2 * BTILE_F4)
#define SMEM_BYTES ((OFF_BIAS4 + 32) * 16)   // 98816

// ---------------------------------------------------------------------------
// Scratch (device globals)
// ---------------------------------------------------------------------------
__device__ float4 g_hp[2][(BB / 32) * (HH / 8) * 2 * 32];          // 131072 f4 each
__device__ float4 g_xp[(size_t)(BB / 32) * TT * (DD / 8) * 2 * 32]; // 4194304 f4
__device__ float4 g_wB[16 * NCH * BTILE_F4];                        // 393216 f4 (6MB)
__device__ float  g_c[BB * HH];

__device__ __forceinline__ float sigm(float x) { return 1.0f / (1.0f + __expf(-x)); }

__device__ __forceinline__ uint32_t smem_u32(const void* p) {
    uint32_t a;
    asm("{ .reg .u64 t; cvta.to.shared.u64 t, %1; cvt.u32.u64 %0, t; }" : "=r"(a) : "l"(p));
    return a;
}

__device__ __forceinline__ uint32_t f2tf32(float x) {
    uint32_t r;
    asm("cvt.rna.tf32.f32 %0, %1;" : "=r"(r) : "f"(x));
    return r;
}

__device__ __forceinline__ void mma_tf32(float* d, const uint4& a,
                                         uint32_t b0, uint32_t b1) {
    asm volatile(
        "mma.sync.aligned.m16n8k8.row.col.f32.tf32.tf32.f32 "
        "{%0,%1,%2,%3}, {%4,%5,%6,%7}, {%8,%9}, {%0,%1,%2,%3};"
        : "+f"(d[0]), "+f"(d[1]), "+f"(d[2]), "+f"(d[3])
        : "r"(a.x), "r"(a.y), "r"(a.z), "r"(a.w), "r"(b0), "r"(b1));
}

__device__ __forceinline__ void cp_async16(uint32_t smem_addr, const void* gptr) {
    asm volatile("cp.async.cg.shared.global [%0], [%1], 16;"
                 :: "r"(smem_addr), "l"(gptr));
}
#define CP_COMMIT() asm volatile("cp.async.commit_group;" ::: "memory")
#define CP_WAIT(n)  asm volatile("cp.async.wait_group %0;" :: "n"(n) : "memory")

// ---------------------------------------------------------------------------
// Prep kernels
// ---------------------------------------------------------------------------
// Weights into fragment order, tf32-rounded.
// f4 idx within (ct, chunk): lane=idx&31, q=(idx>>5)&1, wn=(idx>>6)&3, k8=idx>>8
__global__ void prep_weights(const float* __restrict__ W_ih,
                             const float* __restrict__ W_hh) {
    const int ct = blockIdx.x;      // 0..15
    const int c  = blockIdx.y;      // 0..11
    float4* dst = g_wB + ((size_t)ct * NCH + c) * BTILE_F4;
    for (int idx = threadIdx.x; idx < BTILE_F4; idx += blockDim.x) {
        int lane = idx & 31, q = (idx >> 5) & 1, wn = (idx >> 6) & 3, k8 = idx >> 8;
        int lq = lane >> 2, lr = lane & 3;
        float v[4];
        #pragma unroll
        for (int s = 0; s < 4; s++) {
            int nt = q * 2 + (s >> 1);
            int pair = s & 1;
            int grow = nt * HH + ct * 32 + wn * 8 + lq;   // gate=nt, hcl=wn*8+lq
            int k = c * BK + k8 * 8 + lr + pair * 4;
            float w = (k < HH) ? W_hh[(size_t)grow * HH + k]
                               : W_ih[(size_t)grow * DD + (k - HH)];
            v[s] = __uint_as_float(f2tf32(w));
        }
        dst[idx] = make_float4(v[0], v[1], v[2], v[3]);
    }
}

// x into fragment order, tf32-rounded.
// f4 idx: lane=idx&31, mt=(idx>>5)&1, k8x=(idx>>6)&31, tt=(idx>>11)&63, rowblk=idx>>17
__global__ void prep_x(const float* __restrict__ x) {
    size_t idx = (size_t)blockIdx.x * blockDim.x + threadIdx.x;
    if (idx >= (size_t)(BB / 32) * TT * (DD / 8) * 2 * 32) return;
    int lane = (int)(idx & 31);
    int mt   = (int)((idx >> 5) & 1);
    int k8x  = (int)((idx >> 6) & 31);
    int tt   = (int)((idx >> 11) & 63);
    int rowblk = (int)(idx >> 17);
    int lq = lane >> 2, lr = lane & 3;
    float v[4];
    #pragma unroll
    for (int s = 0; s < 4; s++) {
        int pair = s >> 1, half = s & 1;
        int m = rowblk * 32 + mt * 16 + half * 8 + lq;
        int d = k8x * 8 + lr + pair * 4;
        v[s] = __uint_as_float(f2tf32(x[((size_t)m * TT + tt) * DD + d]));
    }
    g_xp[idx] = make_float4(v[0], v[1], v[2], v[3]);
}

// h0 into fragment order (rounded); c0 natural.
__global__ void init_states(const float* __restrict__ h0, const float* __restrict__ c0) {
    int i = blockIdx.x * blockDim.x + threadIdx.x;
    if (i >= BB * HH) return;
    int m = i / HH, col = i % HH;
    int rowblk = m >> 5, r5 = m & 31;
    int mt = r5 >> 4, half = (r5 >> 3) & 1, lq = r5 & 7;
    int k8 = col >> 3, lr = col & 3, pair = (col >> 2) & 1;
    int s = pair * 2 + half;
    size_t f4 = (((size_t)rowblk * (HH / 8) + k8) * 2 + mt) * 32 + (lq * 4 + lr);
    ((float*)g_hp[0])[f4 * 4 + s] = __uint_as_float(f2tf32(h0[i]));
    g_c[i] = c0[i];
}

// ---------------------------------------------------------------------------
// Fused LSTM step (tf32 mma.sync, fragment-order operands):
//   g = [h | x_t] @ [W_hh | W_ih]^T + b ; gate math; masked state store.
// Grid (16 ct, 16 mtiles) = 256 CTAs, 256 threads, 2 CTAs/SM.
// ---------------------------------------------------------------------------
__global__ __launch_bounds__(256, 2)
void lstm_step_mma(const float* __restrict__ b_ih, const float* __restrict__ b_hh,
                   const int* __restrict__ dones, float* __restrict__ out, int t) {
    extern __shared__ float4 sm4[];
    const uint32_t sb = smem_u32(sm4);
    float* biasS = (float*)(sm4 + OFF_BIAS4);
    const int tid  = threadIdx.x;
    const int wid  = tid >> 5;
    const int lane = tid & 31;
    const int wm   = wid >> 1 >> 1;      // wid>>2: 0..1
    const int wn   = wid & 3;            // 0..3
    const int ct   = blockIdx.x;
    const int c0   = ct * 32;
    const int m0   = blockIdx.y * 64;
    const int rb0  = m0 >> 5;
    const int lq   = lane >> 2;
    const int lr   = lane & 3;

    const float4* __restrict__ hp_in = g_hp[t & 1];
    float* __restrict__ hp_out       = (float*)g_hp[(t + 1) & 1];

    // bias staging: biasS[gate*32 + hcol_local]
    if (tid < 128) {
        int gate = tid >> 5, hl = tid & 31;
        int col = gate * HH + c0 + hl;
        biasS[tid] = b_ih[col] + b_hh[col];
    }

    // ---- cp.async tile loader (all linear fragment-order copies) ----
    auto load_tile = [&](int c, int stage) {
        const uint32_t abase = sb + OFF_A4(stage) * 16;
        const uint32_t bbase = sb + OFF_B4(stage) * 16;
        // A: 2 rowblks x 512 f4 contiguous each
        #pragma unroll
        for (int l = 0; l < 4; l++) {
            int idx = l * 256 + tid;       // 0..1023
            int rbl = idx >> 9;
            int rem = idx & 511;
            const float4* src;
            if (c < 8)
                src = hp_in + ((size_t)(rb0 + rbl) * (HH / 8) + c * 8) * 64 + rem;
            else
                src = g_xp + (((size_t)(rb0 + rbl) * TT + t) * (DD / 8) + (c - 8) * 8) * 64 + rem;
            cp_async16(abase + idx * 16, src);
        }
        // B: 2048 f4 linear
        const float4* bsrc = g_wB + ((size_t)ct * NCH + c) * BTILE_F4;
        #pragma unroll
        for (int l = 0; l < 8; l++) {
            int idx = l * 256 + tid;
            cp_async16(bbase + idx * 16, bsrc + idx);
        }
        CP_COMMIT();
    };

    float acc[2][4][4];
    #pragma unroll
    for (int mt = 0; mt < 2; mt++)
        #pragma unroll
        for (int nt = 0; nt < 4; nt++)
            #pragma unroll
            for (int i = 0; i < 4; i++) acc[mt][nt][i] = 0.0f;

    load_tile(0, 0);

    for (int c = 0; c < NCH; c++) {
        const int stage = c & 1;
        if (c + 1 < NCH) {
            load_tile(c + 1, stage ^ 1);
            CP_WAIT(1);
        } else {
            CP_WAIT(0);
        }
        __syncthreads();

        const uint4* Au = (const uint4*)(sm4 + OFF_A4(stage));
        const uint4* Bu = (const uint4*)(sm4 + OFF_B4(stage));

        #pragma unroll
        for (int k8 = 0; k8 < 8; k8++) {
            uint4 a0 = Au[wm * 512 + k8 * 64 + lane];          // mt=0
            uint4 a1 = Au[wm * 512 + k8 * 64 + 32 + lane];     // mt=1
            uint4 b0 = Bu[k8 * 256 + wn * 64 + lane];          // q=0: nt 0,1
            uint4 b1 = Bu[k8 * 256 + wn * 64 + 32 + lane];     // q=1: nt 2,3
            mma_tf32(acc[0][0], a0, b0.x, b0.y);
            mma_tf32(acc[0][1], a0, b0.z, b0.w);
            mma_tf32(acc[0][2], a0, b1.x, b1.y);
            mma_tf32(acc[0][3], a0, b1.z, b1.w);
            mma_tf32(acc[1][0], a1, b0.x, b0.y);
            mma_tf32(acc[1][1], a1, b0.z, b0.w);
            mma_tf32(acc[1][2], a1, b1.x, b1.y);
            mma_tf32(acc[1][3], a1, b1.z, b1.w);
        }
        __syncthreads();
    }

    // ---- Epilogue: gates in-register (nt == gate) ----
    #pragma unroll
    for (int mt = 0; mt < 2; mt++) {
        #pragma unroll
        for (int half = 0; half < 2; half++) {
            const int m = m0 + wm * 32 + mt * 16 + half * 8 + lq;
            float maskn = 1.0f;
            if (t < TT - 1) maskn = 1.0f - (float)dones[(size_t)m * TT + t];
            #pragma unroll
            for (int ci = 0; ci < 2; ci++) {
                const int idx = half * 2 + ci;
                const int hl = wn * 8 + lr * 2 + ci;
                const int colh = c0 + hl;
                float gi = acc[mt][0][idx] + biasS[0 * 32 + hl];
                float gf = acc[mt][1][idx] + biasS[1 * 32 + hl];
                float gg = acc[mt][2][idx] + biasS[2 * 32 + hl];
                float go = acc[mt][3][idx] + biasS[3 * 32 + hl];
                const size_t sidx = (size_t)m * HH + colh;
                float cp = g_c[sidx];
                float cn = sigm(gf) * cp + sigm(gi) * tanhf(gg);
                float hn = sigm(go) * tanhf(cn);
                g_c[sidx] = cn * maskn;
                // h into fragment-order buffer for next step (rounded, masked)
                int kk7 = lr * 2 + ci;                     // 0..7
                int lr_a = kk7 & 3, pair_a = kk7 >> 2;
                int s = pair_a * 2 + half;
                size_t f4 = (((size_t)((m0 >> 5) + wm) * (HH / 8) + (ct * 4 + wn)) * 2 + mt) * 32
                            + (lq * 4 + lr_a);
                hp_out[f4 * 4 + s] = __uint_as_float(f2tf32(hn)) * maskn;
                out[((size_t)m * TT + t) * HH + colh] = hn;   // full precision
            }
        }
    }
}

// ---------------------------------------------------------------------------
// Copy final states BEFORE LayerNorm: h_n = out[:, T-1, :], c_n = g_c.
// ---------------------------------------------------------------------------
__global__ void copy_states(float* __restrict__ out) {
    int i = blockIdx.x * blockDim.x + threadIdx.x;
    if (i < BB * HH) {
        const size_t base = (size_t)BB * TT * HH;
        int m = i / HH, col = i % HH;
        out[base + i]           = out[((size_t)m * TT + (TT - 1)) * HH + col];
        out[base + BB * HH + i] = g_c[i];
    }
}

// ---------------------------------------------------------------------------
// LayerNorm in-place over H=512. One 128-thread block per row.
// ---------------------------------------------------------------------------
__global__ __launch_bounds__(128)
void ln_kernel(float* __restrict__ out, const float* __restrict__ gamma,
               const float* __restrict__ beta) {
    __shared__ float red[8];
    const int row = blockIdx.x;
    const int tid = threadIdx.x;
    float* p = out + (size_t)row * HH;

    float4 v = ((const float4*)p)[tid];
    float s  = v.x + v.y + v.z + v.w;
    float sq = v.x * v.x + v.y * v.y + v.z * v.z + v.w * v.w;
    #pragma unroll
    for (int o = 16; o > 0; o >>= 1) {
        s  += __shfl_xor_sync(0xFFFFFFFFu, s, o);
        sq += __shfl_xor_sync(0xFFFFFFFFu, sq, o);
    }
    int warp = tid >> 5, lane = tid & 31;
    if (lane == 0) { red[warp] = s; red[4 + warp] = sq; }
    __syncthreads();
    s  = red[0] + red[1] + red[2] + red[3];
    sq = red[4] + red[5] + red[6] + red[7];

    float mu  = s * (1.0f / HH);
    float var = sq * (1.0f / HH) - mu * mu;
    float rr  = rsqrtf(var + LN_EPS);

    float4 gm = ((const float4*)gamma)[tid];
    float4 bt = ((const float4*)beta)[tid];
    float4 y;
    y.x = gm.x * (v.x - mu) * rr + bt.x;
    y.y = gm.y * (v.y - mu) * rr + bt.y;
    y.z = gm.z * (v.z - mu) * rr + bt.z;
    y.w = gm.w * (v.w - mu) * rr + bt.w;
    ((float4*)p)[tid] = y;
}

// ---------------------------------------------------------------------------
// Launch
// ---------------------------------------------------------------------------
extern "C" void kernel_launch(void* const* d_in, const int* in_sizes, int n_in,
                              void* d_out, int out_size) {
    const float* x     = (const float*)d_in[0];
    const float* h0    = (const float*)d_in[1];
    const float* c0    = (const float*)d_in[2];
    const float* W_ih  = (const float*)d_in[3];
    const float* W_hh  = (const float*)d_in[4];
    const float* b_ih  = (const float*)d_in[5];
    const float* b_hh  = (const float*)d_in[6];
    const float* gamma = (const float*)d_in[7];
    const float* beta  = (const float*)d_in[8];
    const int*   dones = (const int*)d_in[9];
    float* out = (float*)d_out;

    cudaFuncSetAttribute(lstm_step_mma, cudaFuncAttributeMaxDynamicSharedMemorySize,
                         SMEM_BYTES);

    init_states<<<(BB * HH + 255) / 256, 256>>>(h0, c0);
    prep_weights<<<dim3(16, NCH), 256>>>(W_ih, W_hh);
    {
        size_t n = (size_t)(BB / 32) * TT * (DD / 8) * 2 * 32;
        prep_x<<<(int)((n + 255) / 256), 256>>>(x);
    }

    dim3 gS(16, 16);   // 256 CTAs
    for (int t = 0; t < TT; ++t)
        lstm_step_mma<<<gS, 256, SMEM_BYTES>>>(b_ih, b_hh, dones, out, t);

    copy_states<<<(BB * HH + 255) / 256, 256>>>(out);
    ln_kernel<<<BB * TT, 128>>>(out, gamma, beta);
}

// round 8
// speedup vs baseline: 4.1769x; 1.1084x over previous
#include <cuda_runtime.h>
#include <cuda_bf16.h>
#include <cstdint>
#include <cstddef>

// Problem constants
#define BB 1024
#define TT 64
#define DD 256
#define HH 512
#define LN_EPS 1e-5f

// Fused step GEMM: C[64 m, 128 n] per CTA, n = 32 hcols x 4 gates.
// K = 768 in 12 chunks of 64. 256 threads = 8 warps (wm 0..1 x wn 0..3).
// Chunks 0..7 = h (barrier-dependent), 8..11 = x (independent).
// Persistent kernel: chunk order per step = [8,9,10,11, 0..7].
#define NCH 12
#define BK 64
#define ATILE_F4 1024
#define BTILE_F4 2048
#define OFF_A4(s) ((s) * ATILE_F4)
#define OFF_B4(s) (2 * ATILE_F4 + (s) * BTILE_F4)
#define OFF_BIAS4 (2 * ATILE_F4 + 2 * BTILE_F4)
#define SMEM_BYTES ((OFF_BIAS4 + 32) * 16)   // 98816
#define NCTAS 256

// ---------------------------------------------------------------------------
// Scratch (device globals)
// ---------------------------------------------------------------------------
__device__ float4 g_hp[2][(BB / 32) * (HH / 8) * 2 * 32];
__device__ float4 g_xp[(size_t)(BB / 32) * TT * (DD / 8) * 2 * 32];
__device__ float4 g_wB[16 * NCH * BTILE_F4];
__device__ float  g_c[BB * HH];
__device__ unsigned g_bar;                       // grid barrier counter

__device__ __forceinline__ float sigm(float x) { return 1.0f / (1.0f + __expf(-x)); }

__device__ __forceinline__ uint32_t smem_u32(const void* p) {
    uint32_t a;
    asm("{ .reg .u64 t; cvta.to.shared.u64 t, %1; cvt.u32.u64 %0, t; }" : "=r"(a) : "l"(p));
    return a;
}

__device__ __forceinline__ uint32_t f2tf32(float x) {
    uint32_t r;
    asm("cvt.rna.tf32.f32 %0, %1;" : "=r"(r) : "f"(x));
    return r;
}

__device__ __forceinline__ void mma_tf32(float* d, const uint4& a,
                                         uint32_t b0, uint32_t b1) {
    asm volatile(
        "mma.sync.aligned.m16n8k8.row.col.f32.tf32.tf32.f32 "
        "{%0,%1,%2,%3}, {%4,%5,%6,%7}, {%8,%9}, {%0,%1,%2,%3};"
        : "+f"(d[0]), "+f"(d[1]), "+f"(d[2]), "+f"(d[3])
        : "r"(a.x), "r"(a.y), "r"(a.z), "r"(a.w), "r"(b0), "r"(b1));
}

__device__ __forceinline__ void cp_async16(uint32_t smem_addr, const void* gptr) {
    asm volatile("cp.async.cg.shared.global [%0], [%1], 16;"
                 :: "r"(smem_addr), "l"(gptr));
}
#define CP_COMMIT() asm volatile("cp.async.commit_group;" ::: "memory")
#define CP_WAIT(n)  asm volatile("cp.async.wait_group %0;" :: "n"(n) : "memory")

// ---------------------------------------------------------------------------
// Prep kernels (identical layouts to R7)
// ---------------------------------------------------------------------------
__global__ void prep_weights(const float* __restrict__ W_ih,
                             const float* __restrict__ W_hh) {
    const int ct = blockIdx.x;      // 0..15
    const int c  = blockIdx.y;      // 0..11
    float4* dst = g_wB + ((size_t)ct * NCH + c) * BTILE_F4;
    for (int idx = threadIdx.x; idx < BTILE_F4; idx += blockDim.x) {
        int lane = idx & 31, q = (idx >> 5) & 1, wn = (idx >> 6) & 3, k8 = idx >> 8;
        int lq = lane >> 2, lr = lane & 3;
        float v[4];
        #pragma unroll
        for (int s = 0; s < 4; s++) {
            int nt = q * 2 + (s >> 1);
            int pair = s & 1;
            int grow = nt * HH + ct * 32 + wn * 8 + lq;
            int k = c * BK + k8 * 8 + lr + pair * 4;
            float w = (k < HH) ? W_hh[(size_t)grow * HH + k]
                               : W_ih[(size_t)grow * DD + (k - HH)];
            v[s] = __uint_as_float(f2tf32(w));
        }
        dst[idx] = make_float4(v[0], v[1], v[2], v[3]);
    }
}

__global__ void prep_x(const float* __restrict__ x) {
    size_t idx = (size_t)blockIdx.x * blockDim.x + threadIdx.x;
    if (idx >= (size_t)(BB / 32) * TT * (DD / 8) * 2 * 32) return;
    int lane = (int)(idx & 31);
    int mt   = (int)((idx >> 5) & 1);
    int k8x  = (int)((idx >> 6) & 31);
    int tt   = (int)((idx >> 11) & 63);
    int rowblk = (int)(idx >> 17);
    int lq = lane >> 2, lr = lane & 3;
    float v[4];
    #pragma unroll
    for (int s = 0; s < 4; s++) {
        int pair = s >> 1, half = s & 1;
        int m = rowblk * 32 + mt * 16 + half * 8 + lq;
        int d = k8x * 8 + lr + pair * 4;
        v[s] = __uint_as_float(f2tf32(x[((size_t)m * TT + tt) * DD + d]));
    }
    g_xp[idx] = make_float4(v[0], v[1], v[2], v[3]);
}

__global__ void init_states(const float* __restrict__ h0, const float* __restrict__ c0) {
    int i = blockIdx.x * blockDim.x + threadIdx.x;
    if (i == 0) g_bar = 0;                       // reset grid barrier each replay
    if (i >= BB * HH) return;
    int m = i / HH, col = i % HH;
    int rowblk = m >> 5, r5 = m & 31;
    int mt = r5 >> 4, half = (r5 >> 3) & 1, lq = r5 & 7;
    int k8 = col >> 3, lr = col & 3, pair = (col >> 2) & 1;
    int s = pair * 2 + half;
    size_t f4 = (((size_t)rowblk * (HH / 8) + k8) * 2 + mt) * 32 + (lq * 4 + lr);
    ((float*)g_hp[0])[f4 * 4 + s] = __uint_as_float(f2tf32(h0[i]));
    g_c[i] = c0[i];
}

// ---------------------------------------------------------------------------
// Persistent fused LSTM: all 64 steps in one launch, software grid barrier.
// Grid (16 ct, 16 mtiles) = 256 CTAs, 256 threads, 2 CTAs/SM (co-resident).
// ---------------------------------------------------------------------------
__global__ __launch_bounds__(256, 2)
void lstm_persist(const float* __restrict__ b_ih, const float* __restrict__ b_hh,
                  const int* __restrict__ dones, float* __restrict__ out) {
    extern __shared__ float4 sm4[];
    const uint32_t sb = smem_u32(sm4);
    float* biasS = (float*)(sm4 + OFF_BIAS4);
    const int tid  = threadIdx.x;
    const int wid  = tid >> 5;
    const int lane = tid & 31;
    const int wm   = wid >> 2;           // 0..1
    const int wn   = wid & 3;            // 0..3
    const int ct   = blockIdx.x;
    const int c0   = ct * 32;
    const int m0   = blockIdx.y * 64;
    const int rb0  = m0 >> 5;
    const int lq   = lane >> 2;
    const int lr   = lane & 3;

    // bias staging (once)
    if (tid < 128) {
        int gate = tid >> 5, hl = tid & 31;
        int col = gate * HH + c0 + hl;
        biasS[tid] = b_ih[col] + b_hh[col];
    }
    __syncthreads();

    for (int t = 0; t < TT; t++) {
        const float4* __restrict__ hp_in = g_hp[t & 1];
        float* __restrict__ hp_out       = (float*)g_hp[(t + 1) & 1];

        auto load_tile = [&](int c, int stage) {
            const uint32_t abase = sb + OFF_A4(stage) * 16;
            const uint32_t bbase = sb + OFF_B4(stage) * 16;
            #pragma unroll
            for (int l = 0; l < 4; l++) {
                int idx = l * 256 + tid;       // 0..1023
                int rbl = idx >> 9;
                int rem = idx & 511;
                const float4* src;
                if (c < 8)
                    src = hp_in + ((size_t)(rb0 + rbl) * (HH / 8) + c * 8) * 64 + rem;
                else
                    src = g_xp + (((size_t)(rb0 + rbl) * TT + t) * (DD / 8) + (c - 8) * 8) * 64 + rem;
                cp_async16(abase + idx * 16, src);
            }
            const float4* bsrc = g_wB + ((size_t)ct * NCH + c) * BTILE_F4;
            #pragma unroll
            for (int l = 0; l < 8; l++) {
                int idx = l * 256 + tid;
                cp_async16(bbase + idx * 16, bsrc + idx);
            }
            CP_COMMIT();
        };

        float acc[2][4][4];
        #pragma unroll
        for (int mt = 0; mt < 2; mt++)
            #pragma unroll
            for (int nt = 0; nt < 4; nt++)
                #pragma unroll
                for (int i = 0; i < 4; i++) acc[mt][nt][i] = 0.0f;

        // chunk order: x chunks first (8..11), then h chunks (0..7)
        load_tile(8, 0);

        #pragma unroll 1
        for (int idx = 0; idx < NCH; idx++) {
            const int stage = idx & 1;
            if (idx + 1 < NCH) {
                const int nc = (idx + 1 < 4) ? (8 + idx + 1) : (idx + 1 - 4);
                if (idx + 1 == 4) {
                    // grid barrier: wait for all step-(t-1) epilogues before
                    // issuing the first h-chunk load.
                    if (tid == 0) {
                        unsigned target = (unsigned)(NCTAS * t);
                        while (*(volatile unsigned*)&g_bar < target) {}
                    }
                    __syncthreads();
                    __threadfence();
                }
                load_tile(nc, stage ^ 1);
                CP_WAIT(1);
            } else {
                CP_WAIT(0);
            }
            __syncthreads();

            const uint4* Au = (const uint4*)(sm4 + OFF_A4(stage));
            const uint4* Bu = (const uint4*)(sm4 + OFF_B4(stage));

            #pragma unroll
            for (int k8 = 0; k8 < 8; k8++) {
                uint4 a0 = Au[wm * 512 + k8 * 64 + lane];
                uint4 a1 = Au[wm * 512 + k8 * 64 + 32 + lane];
                uint4 b0 = Bu[k8 * 256 + wn * 64 + lane];
                uint4 b1 = Bu[k8 * 256 + wn * 64 + 32 + lane];
                mma_tf32(acc[0][0], a0, b0.x, b0.y);
                mma_tf32(acc[0][1], a0, b0.z, b0.w);
                mma_tf32(acc[0][2], a0, b1.x, b1.y);
                mma_tf32(acc[0][3], a0, b1.z, b1.w);
                mma_tf32(acc[1][0], a1, b0.x, b0.y);
                mma_tf32(acc[1][1], a1, b0.z, b0.w);
                mma_tf32(acc[1][2], a1, b1.x, b1.y);
                mma_tf32(acc[1][3], a1, b1.z, b1.w);
            }
            __syncthreads();
        }

        // ---- Epilogue ----
        #pragma unroll
        for (int mt = 0; mt < 2; mt++) {
            #pragma unroll
            for (int half = 0; half < 2; half++) {
                const int m = m0 + wm * 32 + mt * 16 + half * 8 + lq;
                float maskn = 1.0f;
                if (t < TT - 1) maskn = 1.0f - (float)dones[(size_t)m * TT + t];
                const int hl0 = wn * 8 + lr * 2;       // even
                const int colh0 = c0 + hl0;
                const size_t sidx0 = (size_t)m * HH + colh0;
                float2 cpv = *(float2*)(g_c + sidx0);
                float hn2[2], cn2[2];
                #pragma unroll
                for (int ci = 0; ci < 2; ci++) {
                    const int idx = half * 2 + ci;
                    const int hl = hl0 + ci;
                    float gi = acc[mt][0][idx] + biasS[0 * 32 + hl];
                    float gf = acc[mt][1][idx] + biasS[1 * 32 + hl];
                    float gg = acc[mt][2][idx] + biasS[2 * 32 + hl];
                    float go = acc[mt][3][idx] + biasS[3 * 32 + hl];
                    float cp = (ci == 0) ? cpv.x : cpv.y;
                    float cn = sigm(gf) * cp + sigm(gi) * tanhf(gg);
                    float hn = sigm(go) * tanhf(cn);
                    cn2[ci] = cn * maskn;
                    hn2[ci] = hn;
                    // h into fragment-order buffer for next step (rounded, masked)
                    int kk7 = lr * 2 + ci;
                    int lr_a = kk7 & 3, pair_a = kk7 >> 2;
                    int s = pair_a * 2 + half;
                    size_t f4 = (((size_t)(rb0 + wm) * (HH / 8) + (ct * 4 + wn)) * 2 + mt) * 32
                                + (lq * 4 + lr_a);
                    hp_out[f4 * 4 + s] = __uint_as_float(f2tf32(hn)) * maskn;
                }
                *(float2*)(g_c + sidx0) = make_float2(cn2[0], cn2[1]);
                *(float2*)(out + ((size_t)m * TT + t) * HH + colh0) =
                    make_float2(hn2[0], hn2[1]);
            }
        }

        // ---- Grid barrier arrive: writes visible, then count ----
        __threadfence();
        __syncthreads();
        if (tid == 0) atomicAdd(&g_bar, 1u);
    }
}

// ---------------------------------------------------------------------------
// Copy final states BEFORE LayerNorm: h_n = out[:, T-1, :], c_n = g_c.
// ---------------------------------------------------------------------------
__global__ void copy_states(float* __restrict__ out) {
    int i = blockIdx.x * blockDim.x + threadIdx.x;
    if (i < BB * HH) {
        const size_t base = (size_t)BB * TT * HH;
        int m = i / HH, col = i % HH;
        out[base + i]           = out[((size_t)m * TT + (TT - 1)) * HH + col];
        out[base + BB * HH + i] = g_c[i];
    }
}

// ---------------------------------------------------------------------------
// LayerNorm in-place over H=512. One 128-thread block per row.
// ---------------------------------------------------------------------------
__global__ __launch_bounds__(128)
void ln_kernel(float* __restrict__ out, const float* __restrict__ gamma,
               const float* __restrict__ beta) {
    __shared__ float red[8];
    const int row = blockIdx.x;
    const int tid = threadIdx.x;
    float* p = out + (size_t)row * HH;

    float4 v = ((const float4*)p)[tid];
    float s  = v.x + v.y + v.z + v.w;
    float sq = v.x * v.x + v.y * v.y + v.z * v.z + v.w * v.w;
    #pragma unroll
    for (int o = 16; o > 0; o >>= 1) {
        s  += __shfl_xor_sync(0xFFFFFFFFu, s, o);
        sq += __shfl_xor_sync(0xFFFFFFFFu, sq, o);
    }
    int warp = tid >> 5, lane = tid & 31;
    if (lane == 0) { red[warp] = s; red[4 + warp] = sq; }
    __syncthreads();
    s  = red[0] + red[1] + red[2] + red[3];
    sq = red[4] + red[5] + red[6] + red[7];

    float mu  = s * (1.0f / HH);
    float var = sq * (1.0f / HH) - mu * mu;
    float rr  = rsqrtf(var + LN_EPS);

    float4 gm = ((const float4*)gamma)[tid];
    float4 bt = ((const float4*)beta)[tid];
    float4 y;
    y.x = gm.x * (v.x - mu) * rr + bt.x;
    y.y = gm.y * (v.y - mu) * rr + bt.y;
    y.z = gm.z * (v.z - mu) * rr + bt.z;
    y.w = gm.w * (v.w - mu) * rr + bt.w;
    ((float4*)p)[tid] = y;
}

// ---------------------------------------------------------------------------
// Launch
// ---------------------------------------------------------------------------
extern "C" void kernel_launch(void* const* d_in, const int* in_sizes, int n_in,
                              void* d_out, int out_size) {
    const float* x     = (const float*)d_in[0];
    const float* h0    = (const float*)d_in[1];
    const float* c0    = (const float*)d_in[2];
    const float* W_ih  = (const float*)d_in[3];
    const float* W_hh  = (const float*)d_in[4];
    const float* b_ih  = (const float*)d_in[5];
    const float* b_hh  = (const float*)d_in[6];
    const float* gamma = (const float*)d_in[7];
    const float* beta  = (const float*)d_in[8];
    const int*   dones = (const int*)d_in[9];
    float* out = (float*)d_out;

    cudaFuncSetAttribute(lstm_persist, cudaFuncAttributeMaxDynamicSharedMemorySize,
                         SMEM_BYTES);

    init_states<<<(BB * HH + 255) / 256, 256>>>(h0, c0);
    prep_weights<<<dim3(16, NCH), 256>>>(W_ih, W_hh);
    {
        size_t n = (size_t)(BB / 32) * TT * (DD / 8) * 2 * 32;
        prep_x<<<(int)((n + 255) / 256), 256>>>(x);
    }

    lstm_persist<<<dim3(16, 16), 256, SMEM_BYTES>>>(b_ih, b_hh, dones, out);

    copy_states<<<(BB * HH + 255) / 256, 256>>>(out);
    ln_kernel<<<BB * TT, 128>>>(out, gamma, beta);
}

// round 10
// speedup vs baseline: 6.9253x; 1.6580x over previous
#include <cuda_runtime.h>
#include <cuda_fp16.h>
#include <cstdint>
#include <cstddef>

// Problem constants
#define BB 1024
#define TT 64
#define DD 256
#define HH 512
#define LN_EPS 1e-5f

// Fused step GEMM (fp16 mma m16n8k16): C[64 m, 128 n] per CTA,
// n = 32 hcols x 4 gates. K = 768 in 12 chunks of 64 (4 k16 each).
// 256 threads = 8 warps (wm 0..1 x wn 0..3), warp tile 32m x 32n.
// Chunks 0..7 = h (barrier-dependent), 8..11 = x (independent).
// Operands pre-packed in mma-fragment order (uint4 = one A-frag / two B-frags).
#define NCH 12
#define ATILE_U4 512                    // 2 rbl x 4 k16 x 2 mt x 32 lanes
#define BTILE_U4 1024                   // 4 k16 x 4 wn x 2 q x 32 lanes
#define OFF_A4(s) ((s) * ATILE_U4)
#define OFF_B4(s) (2 * ATILE_U4 + (s) * BTILE_U4)
#define OFF_BIAS4 (2 * ATILE_U4 + 2 * BTILE_U4)
#define SMEM_BYTES ((OFF_BIAS4 + 32) * 16)    // 49664
#define NCTAS 256

// ---------------------------------------------------------------------------
// Scratch (device globals)
// ---------------------------------------------------------------------------
__device__ uint4 g_hp[2][(BB / 32) * (HH / 16) * 2 * 32];            // fp16 frag h
__device__ uint4 g_xp[(size_t)(BB / 32) * TT * (DD / 16) * 2 * 32];  // fp16 frag x
__device__ uint4 g_wB[16 * NCH * BTILE_U4];                          // fp16 frag W
__device__ float g_c[BB * HH];
__device__ unsigned g_bar;

__device__ __forceinline__ float sigm(float x) { return 1.0f / (1.0f + __expf(-x)); }

__device__ __forceinline__ uint32_t smem_u32(const void* p) {
    uint32_t a;
    asm("{ .reg .u64 t; cvta.to.shared.u64 t, %1; cvt.u32.u64 %0, t; }" : "=r"(a) : "l"(p));
    return a;
}

__device__ __forceinline__ uint32_t pack_h2(float a, float b) {
    __half2 h = __floats2half2_rn(a, b);
    return *(uint32_t*)&h;
}

__device__ __forceinline__ void mma_f16(float* d, const uint4& a,
                                        uint32_t b0, uint32_t b1) {
    asm volatile(
        "mma.sync.aligned.m16n8k16.row.col.f32.f16.f16.f32 "
        "{%0,%1,%2,%3}, {%4,%5,%6,%7}, {%8,%9}, {%0,%1,%2,%3};"
        : "+f"(d[0]), "+f"(d[1]), "+f"(d[2]), "+f"(d[3])
        : "r"(a.x), "r"(a.y), "r"(a.z), "r"(a.w), "r"(b0), "r"(b1));
}

__device__ __forceinline__ void cp_async16(uint32_t smem_addr, const void* gptr) {
    asm volatile("cp.async.cg.shared.global [%0], [%1], 16;"
                 :: "r"(smem_addr), "l"(gptr));
}
#define CP_COMMIT() asm volatile("cp.async.commit_group;" ::: "memory")
#define CP_WAIT(n)  asm volatile("cp.async.wait_group %0;" :: "n"(n) : "memory")

// ---------------------------------------------------------------------------
// Prep kernels
// ---------------------------------------------------------------------------
// W fragments: g_wB[ct][ch][k16][wn][q][lane]; uint4 slot s:
//   nt = q*2 + (s>>1), hi = s&1; b32 = half2(W[grow][k], W[grow][k+1]),
//   grow = nt*H + ct*32 + wn*8 + lq, k = ch*64 + k16*16 + hi*8 + lr*2.
__global__ void prep_weights(const float* __restrict__ W_ih,
                             const float* __restrict__ W_hh) {
    const int ct = blockIdx.x;      // 0..15
    const int c  = blockIdx.y;      // 0..11
    uint4* dst = g_wB + ((size_t)ct * NCH + c) * BTILE_U4;
    for (int idx = threadIdx.x; idx < BTILE_U4; idx += blockDim.x) {
        int lane = idx & 31, q = (idx >> 5) & 1, wn = (idx >> 6) & 3, k16 = idx >> 8;
        int lq = lane >> 2, lr = lane & 3;
        uint32_t v[4];
        #pragma unroll
        for (int s = 0; s < 4; s++) {
            int nt = q * 2 + (s >> 1);
            int hi = s & 1;
            int grow = nt * HH + ct * 32 + wn * 8 + lq;
            int k = c * 64 + k16 * 16 + hi * 8 + lr * 2;
            float w0, w1;
            if (k < HH) {
                w0 = W_hh[(size_t)grow * HH + k];
                w1 = W_hh[(size_t)grow * HH + k + 1];
            } else {
                w0 = W_ih[(size_t)grow * DD + (k - HH)];
                w1 = W_ih[(size_t)grow * DD + (k - HH) + 1];
            }
            v[s] = pack_h2(w0, w1);
        }
        dst[idx] = make_uint4(v[0], v[1], v[2], v[3]);
    }
}

// x fragments: g_xp[rowblk][tt][k16x][mt][lane]; slot s: half=(s&1), hi=(s>>1);
//   m = rowblk*32 + mt*16 + half*8 + lq, d = k16x*16 + hi*8 + lr*2.
__global__ void prep_x(const float* __restrict__ x) {
    size_t idx = (size_t)blockIdx.x * blockDim.x + threadIdx.x;
    if (idx >= (size_t)(BB / 32) * TT * (DD / 16) * 2 * 32) return;
    int lane = (int)(idx & 31);
    int mt   = (int)((idx >> 5) & 1);
    int k16x = (int)((idx >> 6) & 15);
    int tt   = (int)((idx >> 10) & 63);
    int rowblk = (int)(idx >> 16);
    int lq = lane >> 2, lr = lane & 3;
    uint32_t v[4];
    #pragma unroll
    for (int s = 0; s < 4; s++) {
        int half = s & 1, hi = s >> 1;
        int m = rowblk * 32 + mt * 16 + half * 8 + lq;
        int d = k16x * 16 + hi * 8 + lr * 2;
        const float* src = x + ((size_t)m * TT + tt) * DD + d;
        v[s] = pack_h2(src[0], src[1]);
    }
    g_xp[idx] = make_uint4(v[0], v[1], v[2], v[3]);
}

// h0 into fp16 fragment order; c0 natural; reset barrier.
__global__ void init_states(const float* __restrict__ h0, const float* __restrict__ c0) {
    int i = blockIdx.x * blockDim.x + threadIdx.x;
    if (i == 0) g_bar = 0;
    if (i >= BB * HH) return;
    int m = i / HH, col = i % HH;
    int rowblk = m >> 5, r5 = m & 31;
    int mt = r5 >> 4, half = (r5 >> 3) & 1, lq = r5 & 7;
    int kg = col >> 4, p = col & 15;
    int hi = p >> 3, lr = (p & 7) >> 1, lo = p & 1;
    int s = hi * 2 + half;
    size_t f4 = (((size_t)rowblk * (HH / 16) + kg) * 2 + mt) * 32 + (lq * 4 + lr);
    __half* dst = (__half*)g_hp[0];
    dst[f4 * 8 + s * 2 + lo] = __float2half_rn(h0[i]);
    g_c[i] = c0[i];
}

// ---------------------------------------------------------------------------
// Persistent fused LSTM (fp16 mma): all 64 steps, software grid barrier.
// Grid (16 ct, 16 m) = 256 CTAs, 256 threads, 2 CTAs/SM.
// ---------------------------------------------------------------------------
__global__ __launch_bounds__(256, 2)
void lstm_persist(const float* __restrict__ b_ih, const float* __restrict__ b_hh,
                  const int* __restrict__ dones, float* __restrict__ out) {
    extern __shared__ uint4 sm4[];
    const uint32_t sb = smem_u32(sm4);
    float* biasS = (float*)(sm4 + OFF_BIAS4);
    const int tid  = threadIdx.x;
    const int wid  = tid >> 5;
    const int lane = tid & 31;
    const int wm   = wid >> 2;
    const int wn   = wid & 3;
    const int ct   = blockIdx.x;
    const int c0   = ct * 32;
    const int m0   = blockIdx.y * 64;
    const int rb0  = m0 >> 5;
    const int lq   = lane >> 2;
    const int lr   = lane & 3;

    if (tid < 128) {
        int gate = tid >> 5, hl = tid & 31;
        int col = gate * HH + c0 + hl;
        biasS[tid] = b_ih[col] + b_hh[col];
    }
    __syncthreads();

    for (int t = 0; t < TT; t++) {
        const uint4* __restrict__ hp_in = g_hp[t & 1];
        uint32_t* __restrict__ hp_out   = (uint32_t*)g_hp[(t + 1) & 1];

        auto load_tile = [&](int c, int stage) {
            const uint32_t abase = sb + OFF_A4(stage) * 16;
            const uint32_t bbase = sb + OFF_B4(stage) * 16;
            // A: 2 rowblks x 256 uint4 contiguous each (512 total, 2/thread)
            #pragma unroll
            for (int l = 0; l < 2; l++) {
                int idx = l * 256 + tid;     // 0..511
                int rbl = idx >> 8;
                int rem = idx & 255;
                const uint4* src;
                if (c < 8)
                    src = hp_in + ((size_t)(rb0 + rbl) * (HH / 16) + c * 4) * 64 + rem;
                else
                    src = g_xp + (((size_t)(rb0 + rbl) * TT + t) * (DD / 16) + (c - 8) * 4) * 64 + rem;
                cp_async16(abase + idx * 16, src);
            }
            // B: 1024 uint4 linear (4/thread)
            const uint4* bsrc = g_wB + ((size_t)ct * NCH + c) * BTILE_U4;
            #pragma unroll
            for (int l = 0; l < 4; l++) {
                int idx = l * 256 + tid;
                cp_async16(bbase + idx * 16, bsrc + idx);
            }
            CP_COMMIT();
        };

        float acc[2][4][4];
        #pragma unroll
        for (int mt = 0; mt < 2; mt++)
            #pragma unroll
            for (int nt = 0; nt < 4; nt++)
                #pragma unroll
                for (int i = 0; i < 4; i++) acc[mt][nt][i] = 0.0f;

        // chunk order: x chunks (8..11) first, then h chunks (0..7)
        load_tile(8, 0);

        #pragma unroll 1
        for (int idx = 0; idx < NCH; idx++) {
            const int stage = idx & 1;
            if (idx + 1 < NCH) {
                const int nc = (idx + 1 < 4) ? (8 + idx + 1) : (idx + 1 - 4);
                if (idx + 1 == 4) {
                    // grid barrier before first h-chunk load
                    if (tid == 0) {
                        unsigned target = (unsigned)(NCTAS * t);
                        while (*(volatile unsigned*)&g_bar < target) {}
                    }
                    __syncthreads();
                    __threadfence();
                }
                load_tile(nc, stage ^ 1);
                CP_WAIT(1);
            } else {
                CP_WAIT(0);
            }
            __syncthreads();

            const uint4* Au = sm4 + OFF_A4(stage);
            const uint4* Bu = sm4 + OFF_B4(stage);

            #pragma unroll
            for (int k16 = 0; k16 < 4; k16++) {
                uint4 a0 = Au[wm * 256 + k16 * 64 + lane];        // mt=0
                uint4 a1 = Au[wm * 256 + k16 * 64 + 32 + lane];   // mt=1
                uint4 b0 = Bu[k16 * 256 + wn * 64 + lane];        // q=0: nt 0,1
                uint4 b1 = Bu[k16 * 256 + wn * 64 + 32 + lane];   // q=1: nt 2,3
                mma_f16(acc[0][0], a0, b0.x, b0.y);
                mma_f16(acc[0][1], a0, b0.z, b0.w);
                mma_f16(acc[0][2], a0, b1.x, b1.y);
                mma_f16(acc[0][3], a0, b1.z, b1.w);
                mma_f16(acc[1][0], a1, b0.x, b0.y);
                mma_f16(acc[1][1], a1, b0.z, b0.w);
                mma_f16(acc[1][2], a1, b1.x, b1.y);
                mma_f16(acc[1][3], a1, b1.z, b1.w);
            }
            __syncthreads();
        }

        // ---- Epilogue (C layout identical to tf32 path) ----
        const int kg = ct * 2 + (wn >> 1);          // h-fragment k16 index
        #pragma unroll
        for (int mt = 0; mt < 2; mt++) {
            #pragma unroll
            for (int half = 0; half < 2; half++) {
                const int m = m0 + wm * 32 + mt * 16 + half * 8 + lq;
                float maskn = 1.0f;
                if (t < TT - 1) maskn = 1.0f - (float)dones[(size_t)m * TT + t];
                const int hl0 = wn * 8 + lr * 2;
                const int colh0 = c0 + hl0;
                const size_t sidx0 = (size_t)m * HH + colh0;
                float2 cpv = *(float2*)(g_c + sidx0);
                float hn2[2], cn2[2];
                #pragma unroll
                for (int ci = 0; ci < 2; ci++) {
                    const int idx = half * 2 + ci;
                    const int hl = hl0 + ci;
                    float gi = acc[mt][0][idx] + biasS[0 * 32 + hl];
                    float gf = acc[mt][1][idx] + biasS[1 * 32 + hl];
                    float gg = acc[mt][2][idx] + biasS[2 * 32 + hl];
                    float go = acc[mt][3][idx] + biasS[3 * 32 + hl];
                    float cp = (ci == 0) ? cpv.x : cpv.y;
                    float cn = sigm(gf) * cp + sigm(gi) * tanhf(gg);
                    float hn = sigm(go) * tanhf(cn);
                    cn2[ci] = cn * maskn;
                    hn2[ci] = hn;
                }
                // h pair -> one half2 A-fragment register for next step
                {
                    int s = (wn & 1) * 2 + half;
                    size_t f4 = (((size_t)(rb0 + wm) * (HH / 16) + kg) * 2 + mt) * 32
                                + (lq * 4 + lr);
                    hp_out[f4 * 4 + s] = pack_h2(hn2[0] * maskn, hn2[1] * maskn);
                }
                *(float2*)(g_c + sidx0) = make_float2(cn2[0], cn2[1]);
                *(float2*)(out + ((size_t)m * TT + t) * HH + colh0) =
                    make_float2(hn2[0], hn2[1]);
            }
        }

        __threadfence();
        __syncthreads();
        if (tid == 0) atomicAdd(&g_bar, 1u);
    }
}

// ---------------------------------------------------------------------------
// Copy final states BEFORE LayerNorm: h_n = out[:, T-1, :], c_n = g_c.
// ---------------------------------------------------------------------------
__global__ void copy_states(float* __restrict__ out) {
    int i = blockIdx.x * blockDim.x + threadIdx.x;
    if (i < BB * HH) {
        const size_t base = (size_t)BB * TT * HH;
        int m = i / HH, col = i % HH;
        out[base + i]           = out[((size_t)m * TT + (TT - 1)) * HH + col];
        out[base + BB * HH + i] = g_c[i];
    }
}

// ---------------------------------------------------------------------------
// LayerNorm in-place over H=512. One 128-thread block per row.
// ---------------------------------------------------------------------------
__global__ __launch_bounds__(128)
void ln_kernel(float* __restrict__ out, const float* __restrict__ gamma,
               const float* __restrict__ beta) {
    __shared__ float red[8];
    const int row = blockIdx.x;
    const int tid = threadIdx.x;
    float* p = out + (size_t)row * HH;

    float4 v = ((const float4*)p)[tid];
    float s  = v.x + v.y + v.z + v.w;
    float sq = v.x * v.x + v.y * v.y + v.z * v.z + v.w * v.w;
    #pragma unroll
    for (int o = 16; o > 0; o >>= 1) {
        s  += __shfl_xor_sync(0xFFFFFFFFu, s, o);
        sq += __shfl_xor_sync(0xFFFFFFFFu, sq, o);
    }
    int warp = tid >> 5, lane = tid & 31;
    if (lane == 0) { red[warp] = s; red[4 + warp] = sq; }
    __syncthreads();
    s  = red[0] + red[1] + red[2] + red[3];
    sq = red[4] + red[5] + red[6] + red[7];

    float mu  = s * (1.0f / HH);
    float var = sq * (1.0f / HH) - mu * mu;
    float rr  = rsqrtf(var + LN_EPS);

    float4 gm = ((const float4*)gamma)[tid];
    float4 bt = ((const float4*)beta)[tid];
    float4 y;
    y.x = gm.x * (v.x - mu) * rr + bt.x;
    y.y = gm.y * (v.y - mu) * rr + bt.y;
    y.z = gm.z * (v.z - mu) * rr + bt.z;
    y.w = gm.w * (v.w - mu) * rr + bt.w;
    ((float4*)p)[tid] = y;
}

// ---------------------------------------------------------------------------
// Launch
// ---------------------------------------------------------------------------
extern "C" void kernel_launch(void* const* d_in, const int* in_sizes, int n_in,
                              void* d_out, int out_size) {
    const float* x     = (const float*)d_in[0];
    const float* h0    = (const float*)d_in[1];
    const float* c0    = (const float*)d_in[2];
    const float* W_ih  = (const float*)d_in[3];
    const float* W_hh  = (const float*)d_in[4];
    const float* b_ih  = (const float*)d_in[5];
    const float* b_hh  = (const float*)d_in[6];
    const float* gamma = (const float*)d_in[7];
    const float* beta  = (const float*)d_in[8];
    const int*   dones = (const int*)d_in[9];
    float* out = (float*)d_out;

    cudaFuncSetAttribute(lstm_persist, cudaFuncAttributeMaxDynamicSharedMemorySize,
                         SMEM_BYTES);

    init_states<<<(BB * HH + 255) / 256, 256>>>(h0, c0);
    prep_weights<<<dim3(16, NCH), 256>>>(W_ih, W_hh);
    {
        size_t n = (size_t)(BB / 32) * TT * (DD / 16) * 2 * 32;
        prep_x<<<(int)((n + 255) / 256), 256>>>(x);
    }

    lstm_persist<<<dim3(16, 16), 256, SMEM_BYTES>>>(b_ih, b_hh, dones, out);

    copy_states<<<(BB * HH + 255) / 256, 256>>>(out);
    ln_kernel<<<BB * TT, 128>>>(out, gamma, beta);
}